// round 14
// baseline (speedup 1.0000x reference)
#include <cuda_runtime.h>
#include <cuda_fp16.h>
#include <math.h>
#include <cstdint>

#define S_LEN 4096
#define HIDN  2048
#define NH    16
#define NKV   8
#define DH    128
#define KVW   (NKV*DH)      // 1024
#define NQKV  (HIDN + 2*KVW)  // 4096
// base-2 softmax: exp(s*scale) = 2^(s * SCALE_LOG2E)
#define SCALE_LOG2E (0.08838834764831845f * 1.4426950408889634f)

// -------- scratch (device globals: allocation-free) --------
__device__ __half g_xh [(size_t)S_LEN * HIDN];
__device__ __half g_wq [(size_t)HIDN * HIDN];
__device__ __half g_wk [(size_t)KVW  * HIDN];
__device__ __half g_wv [(size_t)KVW  * HIDN];
__device__ __half g_wo [(size_t)HIDN * HIDN];
__device__ float  g_bias[NQKV];
__device__ __half g_qh [(size_t)S_LEN * HIDN];
__device__ __half g_kh [(size_t)S_LEN * KVW];
__device__ __half g_vh [(size_t)S_LEN * KVW];
__device__ __half g_oh [(size_t)S_LEN * HIDN];

// ---------------- PTX helpers ----------------
__device__ __forceinline__ void mma_h(float* d, const uint32_t* a,
                                      uint32_t b0, uint32_t b1) {
    asm volatile(
        "mma.sync.aligned.m16n8k16.row.col.f32.f16.f16.f32 "
        "{%0,%1,%2,%3}, {%4,%5,%6,%7}, {%8,%9}, {%0,%1,%2,%3};"
        : "+f"(d[0]), "+f"(d[1]), "+f"(d[2]), "+f"(d[3])
        : "r"(a[0]), "r"(a[1]), "r"(a[2]), "r"(a[3]), "r"(b0), "r"(b1));
}
__device__ __forceinline__ void ldsm_x4(uint32_t* r, uint32_t addr) {
    asm volatile("ldmatrix.sync.aligned.m8n8.x4.shared.b16 {%0,%1,%2,%3}, [%4];"
        : "=r"(r[0]), "=r"(r[1]), "=r"(r[2]), "=r"(r[3]) : "r"(addr));
}
__device__ __forceinline__ void ldsm_x4_t(uint32_t* r, uint32_t addr) {
    asm volatile("ldmatrix.sync.aligned.m8n8.x4.trans.shared.b16 {%0,%1,%2,%3}, [%4];"
        : "=r"(r[0]), "=r"(r[1]), "=r"(r[2]), "=r"(r[3]) : "r"(addr));
}
__device__ __forceinline__ void cp16(uint32_t dst, const void* src) {
    asm volatile("cp.async.cg.shared.global [%0], [%1], 16;" :: "r"(dst), "l"(src));
}
__device__ __forceinline__ float ex2f(float x) {
    float r;
    asm("ex2.approx.f32 %0, %1;" : "=f"(r) : "f"(x));
    return r;
}
#define CP_COMMIT() asm volatile("cp.async.commit_group;" ::: "memory")
#define CP_WAIT(n)  asm volatile("cp.async.wait_group %0;" :: "n"(n) : "memory")

// ============================================================
// fused fp32 -> fp16 conversion + bias concat
// ============================================================
#define N4_X  ((S_LEN * HIDN) / 4)
#define N4_WQ ((HIDN * HIDN) / 4)
#define N4_WK ((KVW * HIDN) / 4)
#define N4_W_END (N4_X + 2 * N4_WQ + 2 * N4_WK)
#define N4_TOT   (N4_W_END + NQKV / 4)

__global__ __launch_bounds__(256)
void f2h_all(const float4* __restrict__ x,  const float4* __restrict__ wq,
             const float4* __restrict__ wk, const float4* __restrict__ wv,
             const float4* __restrict__ wo,
             const float* __restrict__ bq, const float* __restrict__ bk,
             const float* __restrict__ bv)
{
    int i = blockIdx.x * blockDim.x + threadIdx.x;
    if (i >= N4_TOT) return;
    if (i >= N4_W_END) {
        int col = (i - N4_W_END) * 4;
        const float* src = (col < HIDN) ? bq + col
                         : (col < HIDN + KVW) ? bk + (col - HIDN)
                         : bv + (col - HIDN - KVW);
        *(float4*)(g_bias + col) = *(const float4*)src;
        return;
    }
    const float4* src;
    __half2* dst;
    int off;
    if (i < N4_X) {
        src = x;  dst = (__half2*)g_xh; off = i;
    } else if (i < N4_X + N4_WQ) {
        src = wq; dst = (__half2*)g_wq; off = i - N4_X;
    } else if (i < N4_X + N4_WQ + N4_WK) {
        src = wk; dst = (__half2*)g_wk; off = i - N4_X - N4_WQ;
    } else if (i < N4_X + N4_WQ + 2 * N4_WK) {
        src = wv; dst = (__half2*)g_wv; off = i - N4_X - N4_WQ - N4_WK;
    } else {
        src = wo; dst = (__half2*)g_wo; off = i - N4_X - N4_WQ - 2 * N4_WK;
    }
    float4 v = src[off];
    dst[2 * off]     = __floats2half2_rn(v.x, v.y);
    dst[2 * off + 1] = __floats2half2_rn(v.z, v.w);
}

// ============================================================
// GEMM (fp16, cp.async 3-stage, BK=64, two barriers per tile).
// MODE 0: C fp32 (+bias param).
// MODE 2: fused QKV. Blocks align with heads (BN = head_dim):
//   q/k blocks run RMSNorm+RoPE in-epilogue and store fp16;
//   v blocks store fp16 with bias.
// BM=BN=128, 256 threads (8 warps 4x2), warp tile 32x64.
// ============================================================
#define GPAD 72
#define G_ASB  (128 * GPAD * 2)
#define G_STGB (2 * G_ASB)
#define G_SMEM (3 * G_STGB)   // 110592 B

template<int MODE>
__global__ __launch_bounds__(256, 2)
void gemm_a(const __half* __restrict__ Ah, const __half* __restrict__ Bh,
            const float* __restrict__ bias, float* __restrict__ C,
            const float* __restrict__ cosb, const float* __restrict__ sinb,
            const float* __restrict__ qw, const float* __restrict__ kw,
            int M, int N, int K)
{
    extern __shared__ __half sm[];
    const uint32_t sbase = (uint32_t)__cvta_generic_to_shared(sm);

    const int tid  = threadIdx.x;
    const int lane = tid & 31, wid = tid >> 5;
    const int g = lane >> 2, t = lane & 3;
    const int wm = wid & 3, wn = wid >> 2;
    const int bm = blockIdx.y * 128, bn = blockIdx.x * 128;
    const int r16 = lane & 15;
    const int q8  = (lane >> 4) << 3;

    const __half* Bsel;
    int bnl;
    if (MODE == 2) {
        if (bn < HIDN)            { Bsel = g_wq; bnl = bn; }
        else if (bn < HIDN + KVW) { Bsel = g_wk; bnl = bn - HIDN; }
        else                      { Bsel = g_wv; bnl = bn - HIDN - KVW; }
    } else {
        Bsel = Bh; bnl = bn;
    }

    float acc[2][8][4];
#pragma unroll
    for (int i = 0; i < 2; i++)
#pragma unroll
        for (int j = 0; j < 8; j++)
#pragma unroll
            for (int c = 0; c < 4; c++) acc[i][j][c] = 0.f;

    auto issue = [&](int k0, int s) {
        const uint32_t sa = sbase + (uint32_t)s * G_STGB;
#pragma unroll
        for (int i = 0; i < 4; i++) {
            int idx = tid + (i << 8);
            int row = idx >> 3, c8 = (idx & 7) << 3;
            uint32_t off = (uint32_t)(row * GPAD + c8) * 2;
            cp16(sa + off,         Ah + (size_t)(bm + row) * K + k0 + c8);
            cp16(sa + G_ASB + off, Bsel + (size_t)(bnl + row) * K + k0 + c8);
        }
        CP_COMMIT();
    };

    const int nk = K >> 6;
    issue(0, 0);
    issue(64, 1);

    const int ab = wm * 32, bb = wn * 64;
    const uint32_t aoff = (uint32_t)((ab + r16) * GPAD + q8) * 2;
    const uint32_t boff = (uint32_t)((bb + r16) * GPAD + q8) * 2;

    for (int it = 0; it < nk; ++it) {
        if (it < nk - 1) CP_WAIT(1); else CP_WAIT(0);
        __syncthreads();
        if (it + 2 < nk) issue((it + 2) << 6, (it + 2) % 3);

        const uint32_t sA = sbase + (uint32_t)(it % 3) * G_STGB;
        const uint32_t sB = sA + G_ASB;

#pragma unroll
        for (int ks = 0; ks < 4; ks++) {
            const uint32_t kb2 = (uint32_t)(ks * 16) * 2;
            uint32_t ah[2][4];
#pragma unroll
            for (int i = 0; i < 2; i++)
                ldsm_x4(ah[i], sA + aoff + kb2 + (uint32_t)(i * 16 * GPAD) * 2);
#pragma unroll
            for (int jp = 0; jp < 4; jp++) {
                uint32_t rb4[4];
                ldsm_x4(rb4, sB + boff + kb2 + (uint32_t)(jp * 16 * GPAD) * 2);
                mma_h(acc[0][2 * jp],     ah[0], rb4[0], rb4[2]);
                mma_h(acc[0][2 * jp + 1], ah[0], rb4[1], rb4[3]);
                mma_h(acc[1][2 * jp],     ah[1], rb4[0], rb4[2]);
                mma_h(acc[1][2 * jp + 1], ah[1], rb4[1], rb4[3]);
            }
        }
        __syncthreads();
    }

    // ---- epilogue ----
    if (MODE == 2) {
        if (bn >= HIDN + KVW) {
            // V: bias + fp16 store
            const int c0 = bn - HIDN - KVW;
#pragma unroll
            for (int j = 0; j < 8; j++) {
                const int cl = wn * 64 + j * 8 + 2 * t;
                const float bx = g_bias[bn + cl], by = g_bias[bn + cl + 1];
#pragma unroll
                for (int i = 0; i < 2; i++) {
                    const int row = bm + wm * 32 + i * 16 + g;
                    *(__half2*)(g_vh + (size_t)row * KVW + c0 + cl) =
                        __floats2half2_rn(acc[i][j][0] + bx, acc[i][j][1] + by);
                    *(__half2*)(g_vh + (size_t)(row + 8) * KVW + c0 + cl) =
                        __floats2half2_rn(acc[i][j][2] + bx, acc[i][j][3] + by);
                }
            }
        } else {
            // q/k: fused bias + RMSNorm + RoPE -> fp16
            const bool isq = (bn < HIDN);
            __half* dsth = isq ? g_qh : g_kh;
            const int hstride = isq ? HIDN : KVW;
            const int c0g = isq ? bn : bn - HIDN;
            const float* w = isq ? qw : kw;
            float* nvbuf = (float*)sm;             // [128][132]
            float* sums  = nvbuf + 128 * 132;      // [128][2]

            const int r0 = wm * 32 + g;
            const int rr[4] = {r0, r0 + 8, r0 + 16, r0 + 24};

            // bias add + partial sum of squares (4 row-slots)
            float ps[4] = {0.f, 0.f, 0.f, 0.f};
#pragma unroll
            for (int j = 0; j < 8; j++) {
                const int cl = wn * 64 + j * 8 + 2 * t;
                const float bx = g_bias[bn + cl], by = g_bias[bn + cl + 1];
#pragma unroll
                for (int i = 0; i < 2; i++) {
                    acc[i][j][0] += bx; acc[i][j][1] += by;
                    acc[i][j][2] += bx; acc[i][j][3] += by;
                    ps[2 * i]     += acc[i][j][0] * acc[i][j][0]
                                   + acc[i][j][1] * acc[i][j][1];
                    ps[2 * i + 1] += acc[i][j][2] * acc[i][j][2]
                                   + acc[i][j][3] * acc[i][j][3];
                }
            }
#pragma unroll
            for (int s = 0; s < 4; s++) {
                ps[s] += __shfl_xor_sync(0xffffffffu, ps[s], 1);
                ps[s] += __shfl_xor_sync(0xffffffffu, ps[s], 2);
            }
            // slot->row map: slots {0,1,2,3} -> rows {r0, r0+8, r0+16, r0+24}
            if (t == 0) {
                sums[rr[0] * 2 + wn] = ps[0];
                sums[rr[1] * 2 + wn] = ps[1];
                sums[rr[2] * 2 + wn] = ps[2];
                sums[rr[3] * 2 + wn] = ps[3];
            }
            __syncthreads();
            float inv[4];
#pragma unroll
            for (int s = 0; s < 4; s++) {
                float tot = sums[rr[s] * 2] + sums[rr[s] * 2 + 1];
                inv[s] = rsqrtf(tot * (1.f / 128.f) + 1e-6f);
            }
            // normalize + stash to smem for cross-warp RoPE pairing
#pragma unroll
            for (int j = 0; j < 8; j++) {
                const int cl = wn * 64 + j * 8 + 2 * t;
                const float w0 = w[cl], w1 = w[cl + 1];
#pragma unroll
                for (int i = 0; i < 2; i++) {
                    float n0 = acc[i][j][0] * w0 * inv[2 * i];
                    float n1 = acc[i][j][1] * w1 * inv[2 * i];
                    float n2 = acc[i][j][2] * w0 * inv[2 * i + 1];
                    float n3 = acc[i][j][3] * w1 * inv[2 * i + 1];
                    acc[i][j][0] = n0; acc[i][j][1] = n1;
                    acc[i][j][2] = n2; acc[i][j][3] = n3;
                    nvbuf[rr[2 * i] * 132 + cl]         = n0;
                    nvbuf[rr[2 * i] * 132 + cl + 1]     = n1;
                    nvbuf[rr[2 * i + 1] * 132 + cl]     = n2;
                    nvbuf[rr[2 * i + 1] * 132 + cl + 1] = n3;
                }
            }
            __syncthreads();
            // rope + fp16 store
            const float sgn = (wn == 0) ? -1.f : 1.f;
#pragma unroll
            for (int j = 0; j < 8; j++) {
                const int cl = wn * 64 + j * 8 + 2 * t;
                const int pc = cl ^ 64;
#pragma unroll
                for (int i = 0; i < 2; i++) {
#pragma unroll
                    for (int hf = 0; hf < 2; hf++) {
                        const int row = rr[2 * i + hf];
                        const int gs  = bm + row;
                        float n0 = acc[i][j][2 * hf], n1 = acc[i][j][2 * hf + 1];
                        float p0 = nvbuf[row * 132 + pc];
                        float p1 = nvbuf[row * 132 + pc + 1];
                        float2 cv = *(const float2*)(cosb + (size_t)gs * DH + cl);
                        float2 sv = *(const float2*)(sinb + (size_t)gs * DH + cl);
                        float o0 = n0 * cv.x + sgn * p0 * sv.x;
                        float o1 = n1 * cv.y + sgn * p1 * sv.y;
                        *(__half2*)(dsth + (size_t)gs * hstride + c0g + cl) =
                            __floats2half2_rn(o0, o1);
                    }
                }
            }
        }
    } else {
#pragma unroll
        for (int j = 0; j < 8; j++) {
            const int col = bn + wn * 64 + j * 8 + 2 * t;
            float2 bv = make_float2(0.f, 0.f);
            if (bias) { bv.x = bias[col]; bv.y = bias[col + 1]; }
#pragma unroll
            for (int i = 0; i < 2; i++) {
                const int row = bm + wm * 32 + i * 16 + g;
                *(float2*)(C + (size_t)row * N + col) =
                    make_float2(acc[i][j][0] + bv.x, acc[i][j][1] + bv.y);
                *(float2*)(C + (size_t)(row + 8) * N + col) =
                    make_float2(acc[i][j][2] + bv.x, acc[i][j][3] + bv.y);
            }
        }
    }
}

// ============================================================
// Flash attention, fp16 mma, causal. BM=128, BN=64.
// Base-2 softmax + skip-rescale fast path. (unchanged)
// ============================================================
#define QSTR 136
#define A_QB   (128 * QSTR * 2)
#define A_KB   (64 * QSTR * 2)
#define A_STGB (2 * A_KB)
#define ATTN_SMEM (A_QB + 2 * A_STGB)   // 104448 B

__global__ __launch_bounds__(256, 2)
void attn_h(const __half* __restrict__ Q, const __half* __restrict__ K,
            const __half* __restrict__ V, __half* __restrict__ Oh)
{
    extern __shared__ __half sh[];
    __half* Qs = sh;
    const uint32_t sbase = (uint32_t)__cvta_generic_to_shared(sh);

    const int tid  = threadIdx.x;
    const int lane = tid & 31, wid = tid >> 5;
    const int g = lane >> 2, t = lane & 3;
    const int h  = blockIdx.y;
    const int tq = (gridDim.x - 1) - blockIdx.x;
    const int row0 = tq * 128;
    const int kh = h >> 1;
    const int row_l = wid * 16;

    const int r16 = lane & 15;
    const int q8  = (lane >> 4) << 3;
    const uint32_t qoff = (uint32_t)((row_l + r16) * QSTR + q8) * 2;
    const uint32_t koff = (uint32_t)(r16 * QSTR + q8) * 2;
    const int vm = lane >> 3, vri = lane & 7;
    const uint32_t voff =
        (uint32_t)((vri + ((vm >> 1) << 3)) * QSTR + ((vm & 1) << 3)) * 2;

    const int njt = 2 * tq + 2;

    auto issue = [&](int jt, int s) {
        const int col0 = jt * 64;
        const uint32_t base = sbase + A_QB + (uint32_t)s * A_STGB;
#pragma unroll
        for (int i = 0; i < 4; i++) {
            int idx = tid + (i << 8);
            int row = idx >> 4, c8 = (idx & 15) << 3;
            uint32_t off = (uint32_t)(row * QSTR + c8) * 2;
            cp16(base + off,        K + (size_t)(col0 + row) * KVW + kh * DH + c8);
            cp16(base + A_KB + off, V + (size_t)(col0 + row) * KVW + kh * DH + c8);
        }
        CP_COMMIT();
    };

#pragma unroll
    for (int it = tid; it < 128 * 16; it += 256) {
        int r = it >> 4, c8 = (it & 15) << 3;
        *(uint4*)(Qs + r * QSTR + c8) =
            *(const uint4*)(Q + (size_t)(row0 + r) * HIDN + h * DH + c8);
    }

    issue(0, 0);
    issue(1, 1);

    float o[16][4];
#pragma unroll
    for (int jj = 0; jj < 16; jj++)
#pragma unroll
        for (int c = 0; c < 4; c++) o[jj][c] = 0.f;
    float m0 = -INFINITY, m1 = -INFINITY, l0 = 0.f, l1 = 0.f;

    for (int jt = 0; jt < njt; jt++) {
        if (jt < njt - 1) CP_WAIT(1); else CP_WAIT(0);
        __syncthreads();

        const bool skip = (jt == 2 * tq + 1 && wid < 4);
        if (!skip) {
            const uint32_t sK = sbase + A_QB + (uint32_t)(jt & 1) * A_STGB;
            const uint32_t sV = sK + A_KB;

            // ---- QK^T ----
            float s[8][4];
#pragma unroll
            for (int j = 0; j < 8; j++)
#pragma unroll
                for (int c = 0; c < 4; c++) s[j][c] = 0.f;

#pragma unroll
            for (int ks = 0; ks < 8; ks++) {
                const uint32_t kb2 = (uint32_t)(ks * 16) * 2;
                uint32_t av[4];
                ldsm_x4(av, sbase + qoff + kb2);
#pragma unroll
                for (int jp = 0; jp < 4; jp++) {
                    uint32_t kb4[4];
                    ldsm_x4(kb4, sK + koff + kb2 + (uint32_t)(jp * 16 * QSTR) * 2);
                    mma_h(s[2 * jp],     av, kb4[0], kb4[2]);
                    mma_h(s[2 * jp + 1], av, kb4[1], kb4[3]);
                }
            }

            // ---- softmax (base-2, streaming) ----
            const bool diag = (jt >= 2 * tq);
            const int crel = (jt - 2 * tq) * 64;
            const int rg = row_l + g;
            float mx0 = -INFINITY, mx1 = -INFINITY;
#pragma unroll
            for (int j = 0; j < 8; j++) {
                float v0 = s[j][0] * SCALE_LOG2E, v1 = s[j][1] * SCALE_LOG2E;
                float v2 = s[j][2] * SCALE_LOG2E, v3 = s[j][3] * SCALE_LOG2E;
                if (diag) {
                    int c = crel + 8 * j + 2 * t;
                    if (c     > rg)     v0 = -1e30f;
                    if (c + 1 > rg)     v1 = -1e30f;
                    if (c     > rg + 8) v2 = -1e30f;
                    if (c + 1 > rg + 8) v3 = -1e30f;
                }
                s[j][0] = v0; s[j][1] = v1; s[j][2] = v2; s[j][3] = v3;
                mx0 = fmaxf(mx0, fmaxf(v0, v1));
                mx1 = fmaxf(mx1, fmaxf(v2, v3));
            }
            mx0 = fmaxf(mx0, __shfl_xor_sync(0xffffffffu, mx0, 1));
            mx0 = fmaxf(mx0, __shfl_xor_sync(0xffffffffu, mx0, 2));
            mx1 = fmaxf(mx1, __shfl_xor_sync(0xffffffffu, mx1, 1));
            mx1 = fmaxf(mx1, __shfl_xor_sync(0xffffffffu, mx1, 2));

            const bool nomax =
                __all_sync(0xffffffffu, (mx0 <= m0) && (mx1 <= m1));
            const float mn0 = nomax ? m0 : fmaxf(m0, mx0);
            const float mn1 = nomax ? m1 : fmaxf(m1, mx1);

            float ls0 = 0.f, ls1 = 0.f;
#pragma unroll
            for (int j = 0; j < 8; j++) {
                float p0 = ex2f(s[j][0] - mn0), p1 = ex2f(s[j][1] - mn0);
                float p2 = ex2f(s[j][2] - mn1), p3 = ex2f(s[j][3] - mn1);
                s[j][0] = p0; s[j][1] = p1; s[j][2] = p2; s[j][3] = p3;
                ls0 += p0 + p1;
                ls1 += p2 + p3;
            }
            ls0 += __shfl_xor_sync(0xffffffffu, ls0, 1);
            ls0 += __shfl_xor_sync(0xffffffffu, ls0, 2);
            ls1 += __shfl_xor_sync(0xffffffffu, ls1, 1);
            ls1 += __shfl_xor_sync(0xffffffffu, ls1, 2);

            if (nomax) {
                l0 += ls0;
                l1 += ls1;
            } else {
                const float al0 = ex2f(m0 - mn0), al1 = ex2f(m1 - mn1);
                l0 = l0 * al0 + ls0;
                l1 = l1 * al1 + ls1;
                m0 = mn0; m1 = mn1;
#pragma unroll
                for (int jj = 0; jj < 16; jj++) {
                    o[jj][0] *= al0; o[jj][1] *= al0;
                    o[jj][2] *= al1; o[jj][3] *= al1;
                }
            }

            // ---- PV ----
#pragma unroll
            for (int s2 = 0; s2 < 4; s2++) {
                __half2 t0 = __floats2half2_rn(s[2 * s2][0],     s[2 * s2][1]);
                __half2 t1 = __floats2half2_rn(s[2 * s2][2],     s[2 * s2][3]);
                __half2 t2 = __floats2half2_rn(s[2 * s2 + 1][0], s[2 * s2 + 1][1]);
                __half2 t3 = __floats2half2_rn(s[2 * s2 + 1][2], s[2 * s2 + 1][3]);
                uint32_t pa[4];
                pa[0] = *(uint32_t*)&t0;
                pa[1] = *(uint32_t*)&t1;
                pa[2] = *(uint32_t*)&t2;
                pa[3] = *(uint32_t*)&t3;
                const uint32_t vrow2 = (uint32_t)(s2 * 16 * QSTR) * 2;
#pragma unroll
                for (int djp = 0; djp < 8; djp++) {
                    uint32_t vb[4];
                    ldsm_x4_t(vb, sV + voff + vrow2 + (uint32_t)(djp * 16) * 2);
                    mma_h(o[2 * djp],     pa, vb[0], vb[2]);
                    mma_h(o[2 * djp + 1], pa, vb[1], vb[3]);
                }
            }
        }
        __syncthreads();
        if (jt + 2 < njt) issue(jt + 2, jt & 1);
    }

    // epilogue
    const float i0 = 1.f / l0, i1 = 1.f / l1;
    const int gr0 = row0 + row_l + g, gr1 = gr0 + 8;
#pragma unroll
    for (int jj = 0; jj < 16; jj++) {
        const int col = h * DH + jj * 8 + 2 * t;
        *(__half2*)(Oh + (size_t)gr0 * HIDN + col) =
            __floats2half2_rn(o[jj][0] * i0, o[jj][1] * i0);
        *(__half2*)(Oh + (size_t)gr1 * HIDN + col) =
            __floats2half2_rn(o[jj][2] * i1, o[jj][3] * i1);
    }
}

// ============================================================
// launch
// ============================================================
extern "C" void kernel_launch(void* const* d_in, const int* in_sizes, int n_in,
                              void* d_out, int out_size)
{
    const float* x    = (const float*)d_in[0];
    const float* cosb = (const float*)d_in[1];
    const float* sinb = (const float*)d_in[2];
    // d_in[3] = mask: ignored (exactly causal, implemented analytically)
    const float* Wq = (const float*)d_in[4];
    const float* bq = (const float*)d_in[5];
    const float* Wk = (const float*)d_in[6];
    const float* bk = (const float*)d_in[7];
    const float* Wv = (const float*)d_in[8];
    const float* bv = (const float*)d_in[9];
    const float* Wo = (const float*)d_in[10];
    const float* qw = (const float*)d_in[11];
    const float* kw = (const float*)d_in[12];
    float* out = (float*)d_out;

    __half *xh, *wo, *qhp, *khp, *vhp, *oh;
    cudaGetSymbolAddress((void**)&xh,  g_xh);
    cudaGetSymbolAddress((void**)&wo,  g_wo);
    cudaGetSymbolAddress((void**)&qhp, g_qh);
    cudaGetSymbolAddress((void**)&khp, g_kh);
    cudaGetSymbolAddress((void**)&vhp, g_vh);
    cudaGetSymbolAddress((void**)&oh,  g_oh);

    cudaFuncSetAttribute(attn_h, cudaFuncAttributeMaxDynamicSharedMemorySize,
                         ATTN_SMEM);
    cudaFuncSetAttribute(gemm_a<0>, cudaFuncAttributeMaxDynamicSharedMemorySize,
                         G_SMEM);
    cudaFuncSetAttribute(gemm_a<2>, cudaFuncAttributeMaxDynamicSharedMemorySize,
                         G_SMEM);

    f2h_all<<<(N4_TOT + 255) / 256, 256>>>((const float4*)x, (const float4*)Wq,
                                           (const float4*)Wk, (const float4*)Wv,
                                           (const float4*)Wo, bq, bk, bv);

    dim3 blk(256);
    // fused QKV projection + RMSNorm + RoPE (q/k) + fp16 V
    gemm_a<2><<<dim3(32, 32), blk, G_SMEM>>>(xh, nullptr, nullptr, nullptr,
                                             cosb, sinb, qw, kw,
                                             S_LEN, NQKV, HIDN);

    attn_h<<<dim3(32, NH), 256, ATTN_SMEM>>>(qhp, khp, vhp, oh);

    gemm_a<0><<<dim3(16, 32), blk, G_SMEM>>>(oh, wo, nullptr, out,
                                             nullptr, nullptr, nullptr, nullptr,
                                             S_LEN, HIDN, HIDN);
}

// round 15
// speedup vs baseline: 1.0173x; 1.0173x over previous
#include <cuda_runtime.h>
#include <cuda_fp16.h>
#include <math.h>
#include <cstdint>

#define S_LEN 4096
#define HIDN  2048
#define NH    16
#define NKV   8
#define DH    128
#define KVW   (NKV*DH)      // 1024
#define NQKV  (HIDN + 2*KVW)  // 4096
// base-2 softmax: exp(s*scale) = 2^(s * SCALE_LOG2E); folded into q.
#define SCALE_LOG2E (0.08838834764831845f * 1.4426950408889634f)

// -------- scratch (device globals: allocation-free) --------
__device__ float  g_q  [(size_t)S_LEN * HIDN];
__device__ float  g_k  [(size_t)S_LEN * KVW];
__device__ __half g_xh [(size_t)S_LEN * HIDN];
__device__ __half g_wq [(size_t)HIDN * HIDN];
__device__ __half g_wk [(size_t)KVW  * HIDN];
__device__ __half g_wv [(size_t)KVW  * HIDN];
__device__ __half g_wo [(size_t)HIDN * HIDN];
__device__ float  g_bias[NQKV];
__device__ __half g_qh [(size_t)S_LEN * HIDN];
__device__ __half g_kh [(size_t)S_LEN * KVW];
__device__ __half g_vh [(size_t)S_LEN * KVW];
__device__ __half g_oh [(size_t)S_LEN * HIDN];

// ---------------- PTX helpers ----------------
__device__ __forceinline__ void mma_h(float* d, const uint32_t* a,
                                      uint32_t b0, uint32_t b1) {
    asm volatile(
        "mma.sync.aligned.m16n8k16.row.col.f32.f16.f16.f32 "
        "{%0,%1,%2,%3}, {%4,%5,%6,%7}, {%8,%9}, {%0,%1,%2,%3};"
        : "+f"(d[0]), "+f"(d[1]), "+f"(d[2]), "+f"(d[3])
        : "r"(a[0]), "r"(a[1]), "r"(a[2]), "r"(a[3]), "r"(b0), "r"(b1));
}
__device__ __forceinline__ void ldsm_x4(uint32_t* r, uint32_t addr) {
    asm volatile("ldmatrix.sync.aligned.m8n8.x4.shared.b16 {%0,%1,%2,%3}, [%4];"
        : "=r"(r[0]), "=r"(r[1]), "=r"(r[2]), "=r"(r[3]) : "r"(addr));
}
__device__ __forceinline__ void ldsm_x4_t(uint32_t* r, uint32_t addr) {
    asm volatile("ldmatrix.sync.aligned.m8n8.x4.trans.shared.b16 {%0,%1,%2,%3}, [%4];"
        : "=r"(r[0]), "=r"(r[1]), "=r"(r[2]), "=r"(r[3]) : "r"(addr));
}
__device__ __forceinline__ void cp16(uint32_t dst, const void* src) {
    asm volatile("cp.async.cg.shared.global [%0], [%1], 16;" :: "r"(dst), "l"(src));
}
__device__ __forceinline__ float ex2f(float x) {
    float r;
    asm("ex2.approx.f32 %0, %1;" : "=f"(r) : "f"(x));
    return r;
}
#define CP_COMMIT() asm volatile("cp.async.commit_group;" ::: "memory")
#define CP_WAIT(n)  asm volatile("cp.async.wait_group %0;" :: "n"(n) : "memory")

// ============================================================
// fused fp32 -> fp16 conversion + bias concat
// ============================================================
#define N4_X  ((S_LEN * HIDN) / 4)
#define N4_WQ ((HIDN * HIDN) / 4)
#define N4_WK ((KVW * HIDN) / 4)
#define N4_W_END (N4_X + 2 * N4_WQ + 2 * N4_WK)
#define N4_TOT   (N4_W_END + NQKV / 4)

__global__ __launch_bounds__(256)
void f2h_all(const float4* __restrict__ x,  const float4* __restrict__ wq,
             const float4* __restrict__ wk, const float4* __restrict__ wv,
             const float4* __restrict__ wo,
             const float* __restrict__ bq, const float* __restrict__ bk,
             const float* __restrict__ bv)
{
    int i = blockIdx.x * blockDim.x + threadIdx.x;
    if (i >= N4_TOT) return;
    if (i >= N4_W_END) {
        int col = (i - N4_W_END) * 4;
        const float* src = (col < HIDN) ? bq + col
                         : (col < HIDN + KVW) ? bk + (col - HIDN)
                         : bv + (col - HIDN - KVW);
        *(float4*)(g_bias + col) = *(const float4*)src;
        return;
    }
    const float4* src;
    __half2* dst;
    int off;
    if (i < N4_X) {
        src = x;  dst = (__half2*)g_xh; off = i;
    } else if (i < N4_X + N4_WQ) {
        src = wq; dst = (__half2*)g_wq; off = i - N4_X;
    } else if (i < N4_X + N4_WQ + N4_WK) {
        src = wk; dst = (__half2*)g_wk; off = i - N4_X - N4_WQ;
    } else if (i < N4_X + N4_WQ + 2 * N4_WK) {
        src = wv; dst = (__half2*)g_wv; off = i - N4_X - N4_WQ - N4_WK;
    } else {
        src = wo; dst = (__half2*)g_wo; off = i - N4_X - N4_WQ - 2 * N4_WK;
    }
    float4 v = src[off];
    dst[2 * off]     = __floats2half2_rn(v.x, v.y);
    dst[2 * off + 1] = __floats2half2_rn(v.z, v.w);
}

// ============================================================
// GEMM (fp16, cp.async 3-stage, BK=64 tiles, two barriers/tile).
// MODE 0: C fp32 (+bias). MODE 2: fused QKV routed (q/k fp32, v fp16).
// BM=BN=128, 256 threads (8 warps 4x2), warp tile 32x64.
// ============================================================
#define GPAD 72
#define G_ASB  (128 * GPAD * 2)
#define G_STGB (2 * G_ASB)
#define G_SMEM (3 * G_STGB)   // 110592 B

template<int MODE>
__global__ __launch_bounds__(256, 2)
void gemm_a(const __half* __restrict__ Ah, const __half* __restrict__ Bh,
            const float* __restrict__ bias, float* __restrict__ C,
            int M, int N, int K)
{
    extern __shared__ __half sm[];
    const uint32_t sbase = (uint32_t)__cvta_generic_to_shared(sm);

    const int tid  = threadIdx.x;
    const int lane = tid & 31, wid = tid >> 5;
    const int g = lane >> 2, t = lane & 3;
    const int wm = wid & 3, wn = wid >> 2;
    const int bm = blockIdx.y * 128, bn = blockIdx.x * 128;
    const int r16 = lane & 15;
    const int q8  = (lane >> 4) << 3;

    const __half* Bsel;
    int bnl;
    if (MODE == 2) {
        if (bn < HIDN)            { Bsel = g_wq; bnl = bn; }
        else if (bn < HIDN + KVW) { Bsel = g_wk; bnl = bn - HIDN; }
        else                      { Bsel = g_wv; bnl = bn - HIDN - KVW; }
    } else {
        Bsel = Bh; bnl = bn;
    }

    float acc[2][8][4];
#pragma unroll
    for (int i = 0; i < 2; i++)
#pragma unroll
        for (int j = 0; j < 8; j++)
#pragma unroll
            for (int c = 0; c < 4; c++) acc[i][j][c] = 0.f;

    auto issue = [&](int k0, int s) {
        const uint32_t sa = sbase + (uint32_t)s * G_STGB;
#pragma unroll
        for (int i = 0; i < 4; i++) {
            int idx = tid + (i << 8);
            int row = idx >> 3, c8 = (idx & 7) << 3;
            uint32_t off = (uint32_t)(row * GPAD + c8) * 2;
            cp16(sa + off,         Ah + (size_t)(bm + row) * K + k0 + c8);
            cp16(sa + G_ASB + off, Bsel + (size_t)(bnl + row) * K + k0 + c8);
        }
        CP_COMMIT();
    };

    const int nk = K >> 6;
    issue(0, 0);
    issue(64, 1);

    const int ab = wm * 32, bb = wn * 64;
    const uint32_t aoff = (uint32_t)((ab + r16) * GPAD + q8) * 2;
    const uint32_t boff = (uint32_t)((bb + r16) * GPAD + q8) * 2;

    for (int it = 0; it < nk; ++it) {
        if (it < nk - 1) CP_WAIT(1); else CP_WAIT(0);
        __syncthreads();
        if (it + 2 < nk) issue((it + 2) << 6, (it + 2) % 3);

        const uint32_t sA = sbase + (uint32_t)(it % 3) * G_STGB;
        const uint32_t sB = sA + G_ASB;

#pragma unroll
        for (int ks = 0; ks < 4; ks++) {
            const uint32_t kb2 = (uint32_t)(ks * 16) * 2;
            uint32_t ah[2][4];
#pragma unroll
            for (int i = 0; i < 2; i++)
                ldsm_x4(ah[i], sA + aoff + kb2 + (uint32_t)(i * 16 * GPAD) * 2);
#pragma unroll
            for (int jp = 0; jp < 4; jp++) {
                uint32_t rb4[4];
                ldsm_x4(rb4, sB + boff + kb2 + (uint32_t)(jp * 16 * GPAD) * 2);
                mma_h(acc[0][2 * jp],     ah[0], rb4[0], rb4[2]);
                mma_h(acc[0][2 * jp + 1], ah[0], rb4[1], rb4[3]);
                mma_h(acc[1][2 * jp],     ah[1], rb4[0], rb4[2]);
                mma_h(acc[1][2 * jp + 1], ah[1], rb4[1], rb4[3]);
            }
        }
        __syncthreads();
    }

    // ---- epilogue ----
    if (MODE == 2) {
        const bool isv = (bn >= HIDN + KVW);
        float* dst32 = (bn < HIDN) ? g_q : g_k;
        const int stride = (bn < HIDN) ? HIDN : KVW;
        const int c0 = (bn < HIDN) ? bn : (bn < HIDN + KVW ? bn - HIDN
                                                           : bn - HIDN - KVW);
#pragma unroll
        for (int j = 0; j < 8; j++) {
            const int cl = wn * 64 + j * 8 + 2 * t;
            const float bx = g_bias[bn + cl], by = g_bias[bn + cl + 1];
#pragma unroll
            for (int i = 0; i < 2; i++) {
                const int row = bm + wm * 32 + i * 16 + g;
                float o0 = acc[i][j][0] + bx, o1 = acc[i][j][1] + by;
                float o2 = acc[i][j][2] + bx, o3 = acc[i][j][3] + by;
                if (isv) {
                    *(__half2*)(g_vh + (size_t)row * KVW + c0 + cl) =
                        __floats2half2_rn(o0, o1);
                    *(__half2*)(g_vh + (size_t)(row + 8) * KVW + c0 + cl) =
                        __floats2half2_rn(o2, o3);
                } else {
                    *(float2*)(dst32 + (size_t)row * stride + c0 + cl) =
                        make_float2(o0, o1);
                    *(float2*)(dst32 + (size_t)(row + 8) * stride + c0 + cl) =
                        make_float2(o2, o3);
                }
            }
        }
    } else {
#pragma unroll
        for (int j = 0; j < 8; j++) {
            const int col = bn + wn * 64 + j * 8 + 2 * t;
            float2 bv = make_float2(0.f, 0.f);
            if (bias) { bv.x = bias[col]; bv.y = bias[col + 1]; }
#pragma unroll
            for (int i = 0; i < 2; i++) {
                const int row = bm + wm * 32 + i * 16 + g;
                *(float2*)(C + (size_t)row * N + col) =
                    make_float2(acc[i][j][0] + bv.x, acc[i][j][1] + bv.y);
                *(float2*)(C + (size_t)(row + 8) * N + col) =
                    make_float2(acc[i][j][2] + bv.x, acc[i][j][3] + bv.y);
            }
        }
    }
}

// ============================================================
// Fused RMSNorm + RoPE: one warp per (token, head) row.
// Q output is pre-scaled by SCALE*log2(e) (folds softmax scaling).
// ============================================================
__global__ __launch_bounds__(256)
void rmsrope_kernel(const float* __restrict__ q, const float* __restrict__ k,
                    __half* __restrict__ qh, __half* __restrict__ kh,
                    const float* __restrict__ cosb, const float* __restrict__ sinb,
                    const float* __restrict__ qw, const float* __restrict__ kw)
{
    const int wid  = threadIdx.x >> 5, lane = threadIdx.x & 31;
    const int s    = blockIdx.x * 8 + wid;
    const int hh   = blockIdx.y;

    const float* base;
    __half* outp;
    const float* w;
    float oscale;
    if (hh < NH) {
        base = q + (size_t)s * HIDN + hh * DH;
        outp = qh + (size_t)s * HIDN + hh * DH;
        w = qw;
        oscale = SCALE_LOG2E;
    } else {
        base = k + (size_t)s * KVW + (hh - NH) * DH;
        outp = kh + (size_t)s * KVW + (hh - NH) * DH;
        w = kw;
        oscale = 1.f;
    }

    float4 v = *(const float4*)(base + 4 * lane);
    float ss = v.x * v.x + v.y * v.y + v.z * v.z + v.w * v.w;
#pragma unroll
    for (int off = 16; off >= 1; off >>= 1)
        ss += __shfl_xor_sync(0xffffffffu, ss, off);
    const float inv = rsqrtf(ss * (1.f / 128.f) + 1e-6f);

    float4 wv = *(const float4*)(w + 4 * lane);
    float4 nv;
    nv.x = wv.x * v.x * inv; nv.y = wv.y * v.y * inv;
    nv.z = wv.z * v.z * inv; nv.w = wv.w * v.w * inv;

    float4 ov;
    ov.x = __shfl_xor_sync(0xffffffffu, nv.x, 16);
    ov.y = __shfl_xor_sync(0xffffffffu, nv.y, 16);
    ov.z = __shfl_xor_sync(0xffffffffu, nv.z, 16);
    ov.w = __shfl_xor_sync(0xffffffffu, nv.w, 16);
    const float sgn = (lane < 16) ? -1.f : 1.f;

    const float4 cv = *(const float4*)(cosb + (size_t)s * DH + 4 * lane);
    const float4 sv = *(const float4*)(sinb + (size_t)s * DH + 4 * lane);
    float r0 = (nv.x * cv.x + sgn * ov.x * sv.x) * oscale;
    float r1 = (nv.y * cv.y + sgn * ov.y * sv.y) * oscale;
    float r2 = (nv.z * cv.z + sgn * ov.z * sv.z) * oscale;
    float r3 = (nv.w * cv.w + sgn * ov.w * sv.w) * oscale;

    __half2 h01 = __floats2half2_rn(r0, r1);
    __half2 h23 = __floats2half2_rn(r2, r3);
    uint2 pack;
    pack.x = *(uint32_t*)&h01;
    pack.y = *(uint32_t*)&h23;
    *(uint2*)(outp + 4 * lane) = pack;
}

// ============================================================
// Flash attention, fp16 mma, causal. BM=128, BN=64.
// Scores arrive pre-scaled (base-2 domain): softmax = mask+max+ex2.
// ============================================================
#define QSTR 136
#define A_QB   (128 * QSTR * 2)
#define A_KB   (64 * QSTR * 2)
#define A_STGB (2 * A_KB)
#define ATTN_SMEM (A_QB + 2 * A_STGB)   // 104448 B

__global__ __launch_bounds__(256, 2)
void attn_h(const __half* __restrict__ Q, const __half* __restrict__ K,
            const __half* __restrict__ V, __half* __restrict__ Oh)
{
    extern __shared__ __half sh[];
    __half* Qs = sh;
    const uint32_t sbase = (uint32_t)__cvta_generic_to_shared(sh);

    const int tid  = threadIdx.x;
    const int lane = tid & 31, wid = tid >> 5;
    const int g = lane >> 2, t = lane & 3;
    const int h  = blockIdx.y;
    const int tq = (gridDim.x - 1) - blockIdx.x;
    const int row0 = tq * 128;
    const int kh = h >> 1;
    const int row_l = wid * 16;

    const int r16 = lane & 15;
    const int q8  = (lane >> 4) << 3;
    const uint32_t qoff = (uint32_t)((row_l + r16) * QSTR + q8) * 2;
    const uint32_t koff = (uint32_t)(r16 * QSTR + q8) * 2;
    const int vm = lane >> 3, vri = lane & 7;
    const uint32_t voff =
        (uint32_t)((vri + ((vm >> 1) << 3)) * QSTR + ((vm & 1) << 3)) * 2;

    const int njt = 2 * tq + 2;

    auto issue = [&](int jt, int s) {
        const int col0 = jt * 64;
        const uint32_t base = sbase + A_QB + (uint32_t)s * A_STGB;
#pragma unroll
        for (int i = 0; i < 4; i++) {
            int idx = tid + (i << 8);
            int row = idx >> 4, c8 = (idx & 15) << 3;
            uint32_t off = (uint32_t)(row * QSTR + c8) * 2;
            cp16(base + off,        K + (size_t)(col0 + row) * KVW + kh * DH + c8);
            cp16(base + A_KB + off, V + (size_t)(col0 + row) * KVW + kh * DH + c8);
        }
        CP_COMMIT();
    };

#pragma unroll
    for (int it = tid; it < 128 * 16; it += 256) {
        int r = it >> 4, c8 = (it & 15) << 3;
        *(uint4*)(Qs + r * QSTR + c8) =
            *(const uint4*)(Q + (size_t)(row0 + r) * HIDN + h * DH + c8);
    }

    issue(0, 0);
    issue(1, 1);

    float o[16][4];
#pragma unroll
    for (int jj = 0; jj < 16; jj++)
#pragma unroll
        for (int c = 0; c < 4; c++) o[jj][c] = 0.f;
    float m0 = -INFINITY, m1 = -INFINITY, l0 = 0.f, l1 = 0.f;

    for (int jt = 0; jt < njt; jt++) {
        if (jt < njt - 1) CP_WAIT(1); else CP_WAIT(0);
        __syncthreads();

        const bool skip = (jt == 2 * tq + 1 && wid < 4);
        if (!skip) {
            const uint32_t sK = sbase + A_QB + (uint32_t)(jt & 1) * A_STGB;
            const uint32_t sV = sK + A_KB;

            // ---- QK^T ----
            float s[8][4];
#pragma unroll
            for (int j = 0; j < 8; j++)
#pragma unroll
                for (int c = 0; c < 4; c++) s[j][c] = 0.f;

#pragma unroll
            for (int ks = 0; ks < 8; ks++) {
                const uint32_t kb2 = (uint32_t)(ks * 16) * 2;
                uint32_t av[4];
                ldsm_x4(av, sbase + qoff + kb2);
#pragma unroll
                for (int jp = 0; jp < 4; jp++) {
                    uint32_t kb4[4];
                    ldsm_x4(kb4, sK + koff + kb2 + (uint32_t)(jp * 16 * QSTR) * 2);
                    mma_h(s[2 * jp],     av, kb4[0], kb4[2]);
                    mma_h(s[2 * jp + 1], av, kb4[1], kb4[3]);
                }
            }

            // ---- softmax (scores pre-scaled to base-2 domain) ----
            const bool diag = (jt >= 2 * tq);
            const int crel = (jt - 2 * tq) * 64;
            const int rg = row_l + g;
            float mx0 = -INFINITY, mx1 = -INFINITY;
#pragma unroll
            for (int j = 0; j < 8; j++) {
                if (diag) {
                    int c = crel + 8 * j + 2 * t;
                    if (c     > rg)     s[j][0] = -1e30f;
                    if (c + 1 > rg)     s[j][1] = -1e30f;
                    if (c     > rg + 8) s[j][2] = -1e30f;
                    if (c + 1 > rg + 8) s[j][3] = -1e30f;
                }
                mx0 = fmaxf(mx0, fmaxf(s[j][0], s[j][1]));
                mx1 = fmaxf(mx1, fmaxf(s[j][2], s[j][3]));
            }
            mx0 = fmaxf(mx0, __shfl_xor_sync(0xffffffffu, mx0, 1));
            mx0 = fmaxf(mx0, __shfl_xor_sync(0xffffffffu, mx0, 2));
            mx1 = fmaxf(mx1, __shfl_xor_sync(0xffffffffu, mx1, 1));
            mx1 = fmaxf(mx1, __shfl_xor_sync(0xffffffffu, mx1, 2));

            const bool nomax =
                __all_sync(0xffffffffu, (mx0 <= m0) && (mx1 <= m1));
            const float mn0 = nomax ? m0 : fmaxf(m0, mx0);
            const float mn1 = nomax ? m1 : fmaxf(m1, mx1);

            float ls0 = 0.f, ls1 = 0.f;
#pragma unroll
            for (int j = 0; j < 8; j++) {
                float p0 = ex2f(s[j][0] - mn0), p1 = ex2f(s[j][1] - mn0);
                float p2 = ex2f(s[j][2] - mn1), p3 = ex2f(s[j][3] - mn1);
                s[j][0] = p0; s[j][1] = p1; s[j][2] = p2; s[j][3] = p3;
                ls0 += p0 + p1;
                ls1 += p2 + p3;
            }
            ls0 += __shfl_xor_sync(0xffffffffu, ls0, 1);
            ls0 += __shfl_xor_sync(0xffffffffu, ls0, 2);
            ls1 += __shfl_xor_sync(0xffffffffu, ls1, 1);
            ls1 += __shfl_xor_sync(0xffffffffu, ls1, 2);

            if (nomax) {
                l0 += ls0;
                l1 += ls1;
            } else {
                const float al0 = ex2f(m0 - mn0), al1 = ex2f(m1 - mn1);
                l0 = l0 * al0 + ls0;
                l1 = l1 * al1 + ls1;
                m0 = mn0; m1 = mn1;
#pragma unroll
                for (int jj = 0; jj < 16; jj++) {
                    o[jj][0] *= al0; o[jj][1] *= al0;
                    o[jj][2] *= al1; o[jj][3] *= al1;
                }
            }

            // ---- PV ----
#pragma unroll
            for (int s2 = 0; s2 < 4; s2++) {
                __half2 t0 = __floats2half2_rn(s[2 * s2][0],     s[2 * s2][1]);
                __half2 t1 = __floats2half2_rn(s[2 * s2][2],     s[2 * s2][3]);
                __half2 t2 = __floats2half2_rn(s[2 * s2 + 1][0], s[2 * s2 + 1][1]);
                __half2 t3 = __floats2half2_rn(s[2 * s2 + 1][2], s[2 * s2 + 1][3]);
                uint32_t pa[4];
                pa[0] = *(uint32_t*)&t0;
                pa[1] = *(uint32_t*)&t1;
                pa[2] = *(uint32_t*)&t2;
                pa[3] = *(uint32_t*)&t3;
                const uint32_t vrow2 = (uint32_t)(s2 * 16 * QSTR) * 2;
#pragma unroll
                for (int djp = 0; djp < 8; djp++) {
                    uint32_t vb[4];
                    ldsm_x4_t(vb, sV + voff + vrow2 + (uint32_t)(djp * 16) * 2);
                    mma_h(o[2 * djp],     pa, vb[0], vb[2]);
                    mma_h(o[2 * djp + 1], pa, vb[1], vb[3]);
                }
            }
        }
        __syncthreads();
        if (jt + 2 < njt) issue(jt + 2, jt & 1);
    }

    // epilogue
    const float i0 = 1.f / l0, i1 = 1.f / l1;
    const int gr0 = row0 + row_l + g, gr1 = gr0 + 8;
#pragma unroll
    for (int jj = 0; jj < 16; jj++) {
        const int col = h * DH + jj * 8 + 2 * t;
        *(__half2*)(Oh + (size_t)gr0 * HIDN + col) =
            __floats2half2_rn(o[jj][0] * i0, o[jj][1] * i0);
        *(__half2*)(Oh + (size_t)gr1 * HIDN + col) =
            __floats2half2_rn(o[jj][2] * i1, o[jj][3] * i1);
    }
}

// ============================================================
// launch
// ============================================================
extern "C" void kernel_launch(void* const* d_in, const int* in_sizes, int n_in,
                              void* d_out, int out_size)
{
    const float* x    = (const float*)d_in[0];
    const float* cosb = (const float*)d_in[1];
    const float* sinb = (const float*)d_in[2];
    // d_in[3] = mask: ignored (exactly causal, implemented analytically)
    const float* Wq = (const float*)d_in[4];
    const float* bq = (const float*)d_in[5];
    const float* Wk = (const float*)d_in[6];
    const float* bk = (const float*)d_in[7];
    const float* Wv = (const float*)d_in[8];
    const float* bv = (const float*)d_in[9];
    const float* Wo = (const float*)d_in[10];
    const float* qw = (const float*)d_in[11];
    const float* kw = (const float*)d_in[12];
    float* out = (float*)d_out;

    float *qp, *kp;
    __half *xh, *wo, *qhp, *khp, *vhp, *oh;
    cudaGetSymbolAddress((void**)&qp,  g_q);
    cudaGetSymbolAddress((void**)&kp,  g_k);
    cudaGetSymbolAddress((void**)&xh,  g_xh);
    cudaGetSymbolAddress((void**)&wo,  g_wo);
    cudaGetSymbolAddress((void**)&qhp, g_qh);
    cudaGetSymbolAddress((void**)&khp, g_kh);
    cudaGetSymbolAddress((void**)&vhp, g_vh);
    cudaGetSymbolAddress((void**)&oh,  g_oh);

    cudaFuncSetAttribute(attn_h, cudaFuncAttributeMaxDynamicSharedMemorySize,
                         ATTN_SMEM);
    cudaFuncSetAttribute(gemm_a<0>, cudaFuncAttributeMaxDynamicSharedMemorySize,
                         G_SMEM);
    cudaFuncSetAttribute(gemm_a<2>, cudaFuncAttributeMaxDynamicSharedMemorySize,
                         G_SMEM);

    f2h_all<<<(N4_TOT + 255) / 256, 256>>>((const float4*)x, (const float4*)Wq,
                                           (const float4*)Wk, (const float4*)Wv,
                                           (const float4*)Wo, bq, bk, bv);

    dim3 blk(256);
    gemm_a<2><<<dim3(32, 32), blk, G_SMEM>>>(xh, nullptr, nullptr, nullptr,
                                             S_LEN, NQKV, HIDN);

    rmsrope_kernel<<<dim3(S_LEN / 8, NH + NKV), 256>>>(qp, kp, qhp, khp,
                                                       cosb, sinb, qw, kw);

    attn_h<<<dim3(32, NH), 256, ATTN_SMEM>>>(qhp, khp, vhp, oh);

    gemm_a<0><<<dim3(16, 32), blk, G_SMEM>>>(oh, wo, nullptr, out,
                                             S_LEN, HIDN, HIDN);
}